// round 13
// baseline (speedup 1.0000x reference)
#include <cuda_runtime.h>
#include <cuda_bf16.h>
#include <cuda_fp16.h>
#include <cstdint>

// Problem constants: N=100000 nodes, E=1.6M edges, D=128.
#define NMAX 100000
#define EMAX 1600000
#define D 128
#define SCAN_B 1024

// ================= scratch (static device globals; zero at module load) ===========
__device__ int   g_deg_out[NMAX];
__device__ int   g_deg_in [NMAX];
__device__ float g_inv_out[NMAX];
__device__ float g_inv_in [NMAX];
__device__ int   g_row_off[NMAX + 1];
__device__ int   g_cursor [NMAX];
__device__ int   g_csr    [EMAX];
__device__ int   g_bsum   [256];
__device__ int   g_bflag  [256];
__device__ __nv_bfloat16 g_hb[(size_t)NMAX * D];  // gemm input (pre-scaled by inv_out)
__device__ __half g_t [(size_t)NMAX * D];         // f16 gather tensor (256B/row)
__device__ float g_colsum [D];
// W fragments per layer (bf16 m16n8k16): [kit(8)][nt2(8)][lane(32)] x uint4
__device__ uint4 g_wfrag  [4 * 2048];

__device__ __forceinline__ uint32_t pk_bf16x2(float lo, float hi) {
    __nv_bfloat162 t = __floats2bfloat162_rn(lo, hi);
    return *(uint32_t*)&t;
}

__device__ __forceinline__ uint32_t pk_f16x2(float lo, float hi) {
    __half2 t = __floats2half2_rn(lo, hi);
    return *(uint32_t*)&t;
}

// m16n8k16 bf16 MMA, fp32 accumulate in place
__device__ __forceinline__ void mma_bf16(float* c, uint32_t a0, uint32_t a1,
                                         uint32_t a2, uint32_t a3,
                                         uint32_t b0, uint32_t b1) {
    asm volatile(
        "mma.sync.aligned.m16n8k16.row.col.f32.bf16.bf16.f32 "
        "{%0,%1,%2,%3}, {%4,%5,%6,%7}, {%8,%9}, {%0,%1,%2,%3};"
        : "+f"(c[0]), "+f"(c[1]), "+f"(c[2]), "+f"(c[3])
        : "r"(a0), "r"(a1), "r"(a2), "r"(a3), "r"(b0), "r"(b1));
}

// cp.async 16B global->shared; src_size=0 zero-fills (for out-of-range rows)
__device__ __forceinline__ void cp_async16(uint32_t saddr, const void* gptr, bool pred) {
    int sz = pred ? 16 : 0;
    asm volatile("cp.async.cg.shared.global [%0], [%1], 16, %2;"
                 :: "r"(saddr), "l"(gptr), "r"(sz));
}
#define CP_COMMIT() asm volatile("cp.async.commit_group;" ::: "memory")
#define CP_WAIT0()  asm volatile("cp.async.wait_group 0;" ::: "memory")
#define CP_WAIT1()  asm volatile("cp.async.wait_group 1;" ::: "memory")

// ================= k_deg: degree histogram + W fragment packing ===================
__global__ void k_deg(const int* __restrict__ src, const int* __restrict__ dst, int e,
                      const float* __restrict__ W1, const float* __restrict__ W2,
                      const float* __restrict__ W3, const float* __restrict__ W4) {
    int i = blockIdx.x * blockDim.x + threadIdx.x;
    if (i < e) {
        atomicAdd(&g_deg_out[src[i]], 1);
        atomicAdd(&g_deg_in [dst[i]], 1);
    }
    if (blockIdx.x < 4) {
        const float* W = (blockIdx.x == 0) ? W1 : (blockIdx.x == 1) ? W2
                       : (blockIdx.x == 2) ? W3 : W4;
        uint4* out = &g_wfrag[(size_t)blockIdx.x * 2048];
        for (int j = threadIdx.x; j < 2048; j += blockDim.x) {
            int lane = j & 31;
            int nt2  = (j >> 5) & 7;
            int kit  = j >> 8;             // 0..7
            int kk = kit * 16 + (lane & 3) * 2;
            int c0 = nt2 * 16 + (lane >> 2);
            uint4 v;
            v.x = pk_bf16x2(W[kk * D + c0],        W[(kk + 1) * D + c0]);
            v.y = pk_bf16x2(W[(kk + 8) * D + c0],  W[(kk + 9) * D + c0]);
            v.z = pk_bf16x2(W[kk * D + c0 + 8],    W[(kk + 1) * D + c0 + 8]);
            v.w = pk_bf16x2(W[(kk + 8) * D + c0 + 8], W[(kk + 9) * D + c0 + 8]);
            out[j] = v;
        }
    }
}

// ================= k_scanf: inv_sqrt + full prefix scan (decoupled aggregates) ====
__global__ void k_scanf(int n) {
    __shared__ int ssc[SCAN_B];
    __shared__ int swr[32];
    int t = threadIdx.x;
    int i = blockIdx.x * SCAN_B + t;

    if (i < n) {
        g_inv_out[i] = rsqrtf((float)max(g_deg_out[i], 1));
        g_inv_in [i] = rsqrtf((float)max(g_deg_in [i], 1));
    }

    int v = (i < n) ? g_deg_in[i] : 0;
    ssc[t] = v;
    __syncthreads();
    for (int off = 1; off < SCAN_B; off <<= 1) {
        int x2 = 0;
        if (t >= off) x2 = ssc[t - off];
        __syncthreads();
        ssc[t] += x2;
        __syncthreads();
    }

    if (t == SCAN_B - 1) {
        g_bsum[blockIdx.x] = ssc[t];
        __threadfence();
        atomicExch(&g_bflag[blockIdx.x], 1);
    }

    int part = 0;
    if (t < blockIdx.x) {
        while (((volatile int*)g_bflag)[t] == 0) {}
        part = ((volatile int*)g_bsum)[t];
    }
    #pragma unroll
    for (int off = 16; off > 0; off >>= 1)
        part += __shfl_down_sync(0xffffffffu, part, off);
    if ((t & 31) == 0) swr[t >> 5] = part;
    __syncthreads();
    if (t < 32) {
        int p = swr[t];
        #pragma unroll
        for (int off = 16; off > 0; off >>= 1)
            p += __shfl_down_sync(0xffffffffu, p, off);
        if (t == 0) swr[0] = p;
    }
    __syncthreads();
    int offset = swr[0];

    if (i < n) g_row_off[i + 1] = ssc[t] + offset;
    if (i == 0) g_row_off[0] = 0;
}

// ================= k_fillw: CSR fill + x prescale (x*inv_out -> bf16 g_hb) ========
__global__ void k_fillw(const int* __restrict__ src, const int* __restrict__ dst, int e,
                        const float* __restrict__ x, int n) {
    int gid = blockIdx.x * blockDim.x + threadIdx.x;
    int stride = gridDim.x * blockDim.x;

    if (gid < e) {
        int d = dst[gid];
        int p = g_row_off[d] + atomicAdd(&g_cursor[d], 1);
        g_csr[p] = src[gid];
    }

    const float4* x4 = (const float4*)x;
    uint2* hb2 = (uint2*)g_hb;
    int tot = n * (D / 4);
    for (int j = gid; j < tot; j += stride) {
        int r = j >> 5;
        float s = g_inv_out[r];
        float4 vv = x4[j];
        uint2 u;
        u.x = pk_bf16x2(vv.x * s, vv.y * s);
        u.y = pk_bf16x2(vv.z * s, vv.w * s);
        hb2[j] = u;
    }
}

// ================= tensor-core GEMM: t = hb @ W (hb pre-scaled), f16 out ==========
#define GM_SW_U4 2048
#define GM_SA_OFF (GM_SW_U4 * 16)            // 32768 B
#define GM_SA_PAD 136                         // bf16 elements per row
#define GM_SA_BYTES (128 * GM_SA_PAD * 2)     // 34816 B per buffer
#define GM_SMEM (GM_SA_OFF + 2 * GM_SA_BYTES) // 102400 B

__global__ void __launch_bounds__(256, 2)
k_gemm_mma(const __nv_bfloat16* __restrict__ hin, const uint4* __restrict__ wfrag,
           __half* __restrict__ tout, int n, int ntiles) {
    extern __shared__ char smem[];
    uint4* sW = (uint4*)smem;
    uint32_t sA_u32 = (uint32_t)__cvta_generic_to_shared(smem + GM_SA_OFF);

    int tid = threadIdx.x;
    int w = tid >> 5, lane = tid & 31;
    int qr = lane >> 2;        // 0..7
    int qc = lane & 3;         // 0..3
    int mrow = (w & 3) * 32;   // warp row base within tile
    int nc2_0 = (w >> 2) * 4;  // warp nt2 base (cols (w>>2)*64)
    int ncol = (w >> 2) * 64;

    for (int i = tid; i < GM_SW_U4; i += 256) sW[i] = wfrag[i];

    int st_r   = tid >> 4;
    int st_c16 = tid & 15;

    {
        int row0 = blockIdx.x * 128;
        #pragma unroll
        for (int k = 0; k < 8; k++) {
            int r = st_r + k * 16;
            int gr = row0 + r;
            cp_async16(sA_u32 + (uint32_t)(r * GM_SA_PAD + st_c16 * 8) * 2,
                       &hin[(size_t)gr * D + st_c16 * 8], gr < n);
        }
        CP_COMMIT();
    }

    int buf = 0;
    for (int tile = blockIdx.x; tile < ntiles; tile += gridDim.x) {
        int row0 = tile * 128;
        int ntile = tile + gridDim.x;

        if (ntile < ntiles) {
            int nrow0 = ntile * 128;
            uint32_t nb = sA_u32 + (buf ^ 1) * GM_SA_BYTES;
            #pragma unroll
            for (int k = 0; k < 8; k++) {
                int r = st_r + k * 16;
                int gr = nrow0 + r;
                cp_async16(nb + (uint32_t)(r * GM_SA_PAD + st_c16 * 8) * 2,
                           &hin[(size_t)gr * D + st_c16 * 8], gr < n);
            }
            CP_COMMIT();
            CP_WAIT1();
        } else {
            CP_WAIT0();
        }
        __syncthreads();   // (A) sA[buf] ready

        const __nv_bfloat16* sA =
            (const __nv_bfloat16*)(smem + GM_SA_OFF + buf * GM_SA_BYTES);

        float acc[2][8][4];
        #pragma unroll
        for (int s = 0; s < 2; s++)
            #pragma unroll
            for (int nt = 0; nt < 8; nt++)
                #pragma unroll
                for (int j = 0; j < 4; j++) acc[s][nt][j] = 0.0f;

        #pragma unroll
        for (int kitg = 0; kitg < 8; kitg++) {
            int kb = kitg * 16 + qc * 2;
            uint32_t a[2][4];
            #pragma unroll
            for (int s = 0; s < 2; s++) {
                int r0 = mrow + s * 16 + qr;
                a[s][0] = *(const uint32_t*)&sA[r0 * GM_SA_PAD + kb];
                a[s][1] = *(const uint32_t*)&sA[(r0 + 8) * GM_SA_PAD + kb];
                a[s][2] = *(const uint32_t*)&sA[r0 * GM_SA_PAD + kb + 8];
                a[s][3] = *(const uint32_t*)&sA[(r0 + 8) * GM_SA_PAD + kb + 8];
            }
            #pragma unroll
            for (int i = 0; i < 4; i++) {
                uint4 bb = sW[(kitg * 8 + nc2_0 + i) * 32 + lane];
                #pragma unroll
                for (int s = 0; s < 2; s++) {
                    mma_bf16(acc[s][2 * i],
                             a[s][0], a[s][1], a[s][2], a[s][3], bb.x, bb.y);
                    mma_bf16(acc[s][2 * i + 1],
                             a[s][0], a[s][1], a[s][2], a[s][3], bb.z, bb.w);
                }
            }
        }

        __syncthreads();   // (B) all reads of sA[buf] done -> reuse as f16 C stage
        __half* sC = (__half*)(smem + GM_SA_OFF + buf * GM_SA_BYTES);

        // write f16 C fragments (32KB tile fits the 34.8KB buffer)
        #pragma unroll
        for (int s = 0; s < 2; s++) {
            int r0 = mrow + s * 16 + qr;
            #pragma unroll
            for (int nt = 0; nt < 8; nt++) {
                int col = ncol + nt * 8 + qc * 2;
                *(uint32_t*)&sC[r0 * 128 + col] =
                    pk_f16x2(acc[s][nt][0], acc[s][nt][1]);
                *(uint32_t*)&sC[(r0 + 8) * 128 + col] =
                    pk_f16x2(acc[s][nt][2], acc[s][nt][3]);
            }
        }
        __syncthreads();   // (C) C tile complete

        // coalesced copy-out: 32KB, 16B per thread x 8
        #pragma unroll
        for (int k = 0; k < 8; k++) {
            int idx = tid + k * 256;
            int r = idx >> 4;
            int gr = row0 + r;
            if (gr < n) {
                uint4 v = ((const uint4*)sC)[idx];
                *(uint4*)&tout[(size_t)gr * D + (idx & 15) * 8] = v;
            }
        }
        __syncthreads();   // (D) copy-out done before next prefetch reuses buffer
        buf ^= 1;
    }
}

// ================= aggregation: warp per node, f16 gathers, HADD2 only ============
// Row = 128 f16 = 256B. Lane16 owns 8 cols (16B uint4 load); halves process
// different 8-edge windows of the SAME node. NO conversions: load -> HADD2.
__global__ void __launch_bounds__(256)
k_agg(const __half* __restrict__ tin, const float* __restrict__ bias,
      __nv_bfloat16* __restrict__ hbout, int n, int last) {
    __shared__ float sCol[D];
    int tid = threadIdx.x;
    if (last) {
        if (tid < D) sCol[tid] = 0.0f;
        __syncthreads();
    }

    int wnode = (blockIdx.x * blockDim.x + tid) >> 5;   // warp = node
    int lane = tid & 31;
    int lane16 = lane & 15;
    int halfsel = (lane >> 4) * 8;                       // 0 or 8: edge window
    bool active = wnode < n;
    int s = 0, deg = 0;
    if (active) { s = g_row_off[wnode]; deg = g_row_off[wnode + 1] - s; }
    int coff = lane16 * 8;                               // f16 col offset (16B)

    __half2 acc[4];
    #pragma unroll
    for (int j = 0; j < 4; j++) acc[j] = __half2(__float2half(0.f), __float2half(0.f));

    for (int base = 0; base < deg; base += 16) {
        int m = deg - base;
        if (m > 16) m = 16;
        int idx = 0;
        if (lane16 < m) idx = g_csr[s + base + lane16];

        // issue ALL 8 gathers before accumulation (MLP = 8)
        uint4 v[8];
        #pragma unroll
        for (int jb = 0; jb < 8; jb++) {
            int j = halfsel + jb;
            int ij = __shfl_sync(0xffffffffu, idx, j);
            v[jb] = make_uint4(0u, 0u, 0u, 0u);
            if (j < m) v[jb] = *(const uint4*)&tin[(size_t)ij * D + coff];
        }
        #pragma unroll
        for (int jb = 0; jb < 8; jb++) {
            __half2* p = (__half2*)&v[jb];
            acc[0] = __hadd2(acc[0], p[0]);
            acc[1] = __hadd2(acc[1], p[1]);
            acc[2] = __hadd2(acc[2], p[2]);
            acc[3] = __hadd2(acc[3], p[3]);
        }
    }

    // cross-half reduction (halves hold same cols, different edges)
    #pragma unroll
    for (int j = 0; j < 4; j++) {
        uint32_t u = *(uint32_t*)&acc[j];
        uint32_t o = __shfl_xor_sync(0xffffffffu, u, 16);
        acc[j] = __hadd2(acc[j], *(__half2*)&o);
    }

    if (active && lane < 16) {
        float a[8];
        #pragma unroll
        for (int j = 0; j < 4; j++) {
            float2 f = __half22float2(acc[j]);
            a[2 * j] = f.x; a[2 * j + 1] = f.y;
        }
        float inv = g_inv_in[wnode];
        float o[8];
        #pragma unroll
        for (int j = 0; j < 8; j++)
            o[j] = fmaxf(fmaf(a[j], inv, bias[coff + j]), 0.f);

        if (!last) {
            float so = g_inv_out[wnode];   // pre-scale for next gemm
            uint4 u;
            u.x = pk_bf16x2(o[0] * so, o[1] * so);
            u.y = pk_bf16x2(o[2] * so, o[3] * so);
            u.z = pk_bf16x2(o[4] * so, o[5] * so);
            u.w = pk_bf16x2(o[6] * so, o[7] * so);
            *(uint4*)&hbout[(size_t)wnode * D + coff] = u;
        } else {
            #pragma unroll
            for (int j = 0; j < 8; j++) atomicAdd(&sCol[coff + j], o[j]);
        }
    }

    if (last) {
        __syncthreads();
        if (tid < D) atomicAdd(&g_colsum[tid], sCol[tid]);
    }
}

// ================= epilogue =======================================================
__global__ void k_mlp(const float* __restrict__ Wl1, const float* __restrict__ bl1,
                      const float* __restrict__ Wl2, const float* __restrict__ bl2,
                      const float* __restrict__ Wo,  const float* __restrict__ bo,
                      float* __restrict__ out, int n) {
    __shared__ float s0[D], s1[D], s2[D];
    int t = threadIdx.x;
    s0[t] = g_colsum[t] * (1.0f / (float)n);
    __syncthreads();

    float a = bl1[t];
    for (int k = 0; k < D; k++) a = fmaf(s0[k], Wl1[k * D + t], a);
    s1[t] = fmaxf(a, 0.f);
    __syncthreads();

    float a2 = bl2[t];
    for (int k = 0; k < D; k++) a2 = fmaf(s1[k], Wl2[k * D + t], a2);
    s2[t] = fmaxf(a2, 0.f) * Wo[t];
    __syncthreads();

    for (int off = 64; off > 0; off >>= 1) {
        if (t < off) s2[t] += s2[t + off];
        __syncthreads();
    }
    if (t == 0) out[0] = s2[0] + bo[0];
}

// Tail cleanup: re-zero scratch for the NEXT graph replay.
__global__ void k_clean(int n) {
    int i = blockIdx.x * blockDim.x + threadIdx.x;
    if (i < n) { g_deg_out[i] = 0; g_deg_in[i] = 0; g_cursor[i] = 0; }
    if (i < D) g_colsum[i] = 0.0f;
    if (i < 256) g_bflag[i] = 0;
}

// ================= launch =========================================================
extern "C" void kernel_launch(void* const* d_in, const int* in_sizes, int n_in,
                              void* d_out, int out_size) {
    const float* x   = (const float*)d_in[0];
    const int*   src = (const int*)  d_in[1];
    const int*   dst = (const int*)  d_in[2];
    const float* W1  = (const float*)d_in[3];
    const float* b1  = (const float*)d_in[4];
    const float* W2  = (const float*)d_in[5];
    const float* b2  = (const float*)d_in[6];
    const float* W3  = (const float*)d_in[7];
    const float* b3  = (const float*)d_in[8];
    const float* W4  = (const float*)d_in[9];
    const float* b4  = (const float*)d_in[10];
    const float* Wl1 = (const float*)d_in[11];
    const float* bl1 = (const float*)d_in[12];
    const float* Wl2 = (const float*)d_in[13];
    const float* bl2 = (const float*)d_in[14];
    const float* Wo  = (const float*)d_in[15];
    const float* bo  = (const float*)d_in[16];
    float* out = (float*)d_out;

    int n = in_sizes[0] / D;
    int e = in_sizes[1];

    cudaFuncSetAttribute(k_gemm_mma, cudaFuncAttributeMaxDynamicSharedMemorySize,
                         GM_SMEM);

    __nv_bfloat16* hb;
    __half* t;
    uint4* wf;
    cudaGetSymbolAddress((void**)&hb, g_hb);
    cudaGetSymbolAddress((void**)&t,  g_t);
    cudaGetSymbolAddress((void**)&wf, g_wfrag);

    int nb = (n + SCAN_B - 1) / SCAN_B;
    int ntiles = (n + 127) / 128;
    int ggrid  = ntiles < 296 ? ntiles : 296;
    int agg_grid = (n * 32 + 255) / 256;

    k_deg   <<<(e + 255) / 256, 256>>>(src, dst, e, W1, W2, W3, W4);  // 0
    k_scanf <<<nb, SCAN_B>>>(n);                                      // 1
    k_fillw <<<(e + 255) / 256, 256>>>(src, dst, e, x, n);            // 2

    // layer 1
    k_gemm_mma<<<ggrid, 256, GM_SMEM>>>(hb, wf + 0 * 2048, t, n, ntiles); // 3 <- ncu
    k_agg     <<<agg_grid, 256>>>(t, b1, hb, n, 0);
    // layer 2
    k_gemm_mma<<<ggrid, 256, GM_SMEM>>>(hb, wf + 1 * 2048, t, n, ntiles);
    k_agg     <<<agg_grid, 256>>>(t, b2, hb, n, 0);
    // layer 3
    k_gemm_mma<<<ggrid, 256, GM_SMEM>>>(hb, wf + 2 * 2048, t, n, ntiles);
    k_agg     <<<agg_grid, 256>>>(t, b3, hb, n, 0);
    // layer 4 (column-sum only)
    k_gemm_mma<<<ggrid, 256, GM_SMEM>>>(hb, wf + 3 * 2048, t, n, ntiles);
    k_agg     <<<agg_grid, 256>>>(t, b4, hb, n, 1);

    k_mlp  <<<1, D>>>(Wl1, bl1, Wl2, bl2, Wo, bo, out, n);
    k_clean<<<(n + 255) / 256, 256>>>(n);
}

// round 14
// speedup vs baseline: 1.1864x; 1.1864x over previous
#include <cuda_runtime.h>
#include <cuda_bf16.h>
#include <cuda_fp16.h>
#include <cstdint>

// Problem constants: N=100000 nodes, E=1.6M edges, D=128.
#define NMAX 100000
#define EMAX 1600000
#define D 128
#define SCAN_B 1024

// ================= scratch (static device globals; zero at module load) ===========
__device__ int   g_deg_out[NMAX];
__device__ int   g_deg_in [NMAX];
__device__ float g_inv_out[NMAX];
__device__ float g_inv_in [NMAX];
__device__ int   g_row_off[NMAX + 1];
__device__ int   g_cursor [NMAX];
__device__ int   g_csr    [EMAX];
__device__ int   g_bsum   [256];
__device__ int   g_bflag  [256];
__device__ __nv_bfloat16 g_hb[(size_t)NMAX * D];  // gemm input (pre-scaled by inv_out)
__device__ uint8_t g_t [(size_t)NMAX * D];        // e4m3 gather tensor (128B/row)
__device__ float g_colsum [D];
// W fragments per layer (bf16 m16n8k16): [kit(8)][nt2(8)][lane(32)] x uint4
__device__ uint4 g_wfrag  [4 * 2048];

__device__ __forceinline__ uint32_t pk_bf16x2(float lo, float hi) {
    __nv_bfloat162 t = __floats2bfloat162_rn(lo, hi);
    return *(uint32_t*)&t;
}

// two f32 -> packed e4m3x2 (low byte = lo)
__device__ __forceinline__ uint16_t pk_e4m3x2(float lo, float hi) {
    uint16_t r;
    asm("cvt.rn.satfinite.e4m3x2.f32 %0, %1, %2;" : "=h"(r) : "f"(hi), "f"(lo));
    return r;
}

// packed e4m3x2 -> f16x2 (low e4m3 -> low f16)
__device__ __forceinline__ __half2 e4m3x2_h2(uint16_t u) {
    uint32_t r;
    asm("cvt.rn.f16x2.e4m3x2 %0, %1;" : "=r"(r) : "h"(u));
    return *(__half2*)&r;
}

// m16n8k16 bf16 MMA, fp32 accumulate in place
__device__ __forceinline__ void mma_bf16(float* c, uint32_t a0, uint32_t a1,
                                         uint32_t a2, uint32_t a3,
                                         uint32_t b0, uint32_t b1) {
    asm volatile(
        "mma.sync.aligned.m16n8k16.row.col.f32.bf16.bf16.f32 "
        "{%0,%1,%2,%3}, {%4,%5,%6,%7}, {%8,%9}, {%0,%1,%2,%3};"
        : "+f"(c[0]), "+f"(c[1]), "+f"(c[2]), "+f"(c[3])
        : "r"(a0), "r"(a1), "r"(a2), "r"(a3), "r"(b0), "r"(b1));
}

// cp.async 16B global->shared; src_size=0 zero-fills (for out-of-range rows)
__device__ __forceinline__ void cp_async16(uint32_t saddr, const void* gptr, bool pred) {
    int sz = pred ? 16 : 0;
    asm volatile("cp.async.cg.shared.global [%0], [%1], 16, %2;"
                 :: "r"(saddr), "l"(gptr), "r"(sz));
}
#define CP_COMMIT() asm volatile("cp.async.commit_group;" ::: "memory")
#define CP_WAIT0()  asm volatile("cp.async.wait_group 0;" ::: "memory")
#define CP_WAIT1()  asm volatile("cp.async.wait_group 1;" ::: "memory")

// ================= k_deg: degree histogram + W fragment packing ===================
__global__ void k_deg(const int* __restrict__ src, const int* __restrict__ dst, int e,
                      const float* __restrict__ W1, const float* __restrict__ W2,
                      const float* __restrict__ W3, const float* __restrict__ W4) {
    int i = blockIdx.x * blockDim.x + threadIdx.x;
    if (i < e) {
        atomicAdd(&g_deg_out[src[i]], 1);
        atomicAdd(&g_deg_in [dst[i]], 1);
    }
    if (blockIdx.x < 4) {
        const float* W = (blockIdx.x == 0) ? W1 : (blockIdx.x == 1) ? W2
                       : (blockIdx.x == 2) ? W3 : W4;
        uint4* out = &g_wfrag[(size_t)blockIdx.x * 2048];
        for (int j = threadIdx.x; j < 2048; j += blockDim.x) {
            int lane = j & 31;
            int nt2  = (j >> 5) & 7;
            int kit  = j >> 8;             // 0..7
            int kk = kit * 16 + (lane & 3) * 2;
            int c0 = nt2 * 16 + (lane >> 2);
            uint4 v;
            v.x = pk_bf16x2(W[kk * D + c0],        W[(kk + 1) * D + c0]);
            v.y = pk_bf16x2(W[(kk + 8) * D + c0],  W[(kk + 9) * D + c0]);
            v.z = pk_bf16x2(W[kk * D + c0 + 8],    W[(kk + 1) * D + c0 + 8]);
            v.w = pk_bf16x2(W[(kk + 8) * D + c0 + 8], W[(kk + 9) * D + c0 + 8]);
            out[j] = v;
        }
    }
}

// ================= k_scanf: inv_sqrt + full prefix scan (decoupled aggregates) ====
__global__ void k_scanf(int n) {
    __shared__ int ssc[SCAN_B];
    __shared__ int swr[32];
    int t = threadIdx.x;
    int i = blockIdx.x * SCAN_B + t;

    if (i < n) {
        g_inv_out[i] = rsqrtf((float)max(g_deg_out[i], 1));
        g_inv_in [i] = rsqrtf((float)max(g_deg_in [i], 1));
    }

    int v = (i < n) ? g_deg_in[i] : 0;
    ssc[t] = v;
    __syncthreads();
    for (int off = 1; off < SCAN_B; off <<= 1) {
        int x2 = 0;
        if (t >= off) x2 = ssc[t - off];
        __syncthreads();
        ssc[t] += x2;
        __syncthreads();
    }

    if (t == SCAN_B - 1) {
        g_bsum[blockIdx.x] = ssc[t];
        __threadfence();
        atomicExch(&g_bflag[blockIdx.x], 1);
    }

    int part = 0;
    if (t < blockIdx.x) {
        while (((volatile int*)g_bflag)[t] == 0) {}
        part = ((volatile int*)g_bsum)[t];
    }
    #pragma unroll
    for (int off = 16; off > 0; off >>= 1)
        part += __shfl_down_sync(0xffffffffu, part, off);
    if ((t & 31) == 0) swr[t >> 5] = part;
    __syncthreads();
    if (t < 32) {
        int p = swr[t];
        #pragma unroll
        for (int off = 16; off > 0; off >>= 1)
            p += __shfl_down_sync(0xffffffffu, p, off);
        if (t == 0) swr[0] = p;
    }
    __syncthreads();
    int offset = swr[0];

    if (i < n) g_row_off[i + 1] = ssc[t] + offset;
    if (i == 0) g_row_off[0] = 0;
}

// ================= k_fillw: CSR fill + x prescale (x*inv_out -> bf16 g_hb) ========
__global__ void k_fillw(const int* __restrict__ src, const int* __restrict__ dst, int e,
                        const float* __restrict__ x, int n) {
    int gid = blockIdx.x * blockDim.x + threadIdx.x;
    int stride = gridDim.x * blockDim.x;

    if (gid < e) {
        int d = dst[gid];
        int p = g_row_off[d] + atomicAdd(&g_cursor[d], 1);
        g_csr[p] = src[gid];
    }

    const float4* x4 = (const float4*)x;
    uint2* hb2 = (uint2*)g_hb;
    int tot = n * (D / 4);
    for (int j = gid; j < tot; j += stride) {
        int r = j >> 5;
        float s = g_inv_out[r];
        float4 vv = x4[j];
        uint2 u;
        u.x = pk_bf16x2(vv.x * s, vv.y * s);
        u.y = pk_bf16x2(vv.z * s, vv.w * s);
        hb2[j] = u;
    }
}

// ================= tensor-core GEMM: t = hb @ W (hb pre-scaled), e4m3 out =========
#define GM_SW_U4 2048
#define GM_SA_OFF (GM_SW_U4 * 16)            // 32768 B
#define GM_SA_PAD 136                         // bf16 elements per row
#define GM_SA_BYTES (128 * GM_SA_PAD * 2)     // 34816 B per buffer
#define GM_SMEM (GM_SA_OFF + 2 * GM_SA_BYTES) // 102400 B

__global__ void __launch_bounds__(256, 2)
k_gemm_mma(const __nv_bfloat16* __restrict__ hin, const uint4* __restrict__ wfrag,
           uint8_t* __restrict__ tout, int n, int ntiles) {
    extern __shared__ char smem[];
    uint4* sW = (uint4*)smem;
    uint32_t sA_u32 = (uint32_t)__cvta_generic_to_shared(smem + GM_SA_OFF);

    int tid = threadIdx.x;
    int w = tid >> 5, lane = tid & 31;
    int qr = lane >> 2;        // 0..7
    int qc = lane & 3;         // 0..3
    int mrow = (w & 3) * 32;   // warp row base within tile
    int nc2_0 = (w >> 2) * 4;  // warp nt2 base (cols (w>>2)*64)
    int ncol = (w >> 2) * 64;

    for (int i = tid; i < GM_SW_U4; i += 256) sW[i] = wfrag[i];

    int st_r   = tid >> 4;
    int st_c16 = tid & 15;

    {
        int row0 = blockIdx.x * 128;
        #pragma unroll
        for (int k = 0; k < 8; k++) {
            int r = st_r + k * 16;
            int gr = row0 + r;
            cp_async16(sA_u32 + (uint32_t)(r * GM_SA_PAD + st_c16 * 8) * 2,
                       &hin[(size_t)gr * D + st_c16 * 8], gr < n);
        }
        CP_COMMIT();
    }

    int buf = 0;
    for (int tile = blockIdx.x; tile < ntiles; tile += gridDim.x) {
        int row0 = tile * 128;
        int ntile = tile + gridDim.x;

        if (ntile < ntiles) {
            int nrow0 = ntile * 128;
            uint32_t nb = sA_u32 + (buf ^ 1) * GM_SA_BYTES;
            #pragma unroll
            for (int k = 0; k < 8; k++) {
                int r = st_r + k * 16;
                int gr = nrow0 + r;
                cp_async16(nb + (uint32_t)(r * GM_SA_PAD + st_c16 * 8) * 2,
                           &hin[(size_t)gr * D + st_c16 * 8], gr < n);
            }
            CP_COMMIT();
            CP_WAIT1();
        } else {
            CP_WAIT0();
        }
        __syncthreads();   // (A) sA[buf] ready

        const __nv_bfloat16* sA =
            (const __nv_bfloat16*)(smem + GM_SA_OFF + buf * GM_SA_BYTES);

        float acc[2][8][4];
        #pragma unroll
        for (int s = 0; s < 2; s++)
            #pragma unroll
            for (int nt = 0; nt < 8; nt++)
                #pragma unroll
                for (int j = 0; j < 4; j++) acc[s][nt][j] = 0.0f;

        #pragma unroll
        for (int kitg = 0; kitg < 8; kitg++) {
            int kb = kitg * 16 + qc * 2;
            uint32_t a[2][4];
            #pragma unroll
            for (int s = 0; s < 2; s++) {
                int r0 = mrow + s * 16 + qr;
                a[s][0] = *(const uint32_t*)&sA[r0 * GM_SA_PAD + kb];
                a[s][1] = *(const uint32_t*)&sA[(r0 + 8) * GM_SA_PAD + kb];
                a[s][2] = *(const uint32_t*)&sA[r0 * GM_SA_PAD + kb + 8];
                a[s][3] = *(const uint32_t*)&sA[(r0 + 8) * GM_SA_PAD + kb + 8];
            }
            #pragma unroll
            for (int i = 0; i < 4; i++) {
                uint4 bb = sW[(kitg * 8 + nc2_0 + i) * 32 + lane];
                #pragma unroll
                for (int s = 0; s < 2; s++) {
                    mma_bf16(acc[s][2 * i],
                             a[s][0], a[s][1], a[s][2], a[s][3], bb.x, bb.y);
                    mma_bf16(acc[s][2 * i + 1],
                             a[s][0], a[s][1], a[s][2], a[s][3], bb.z, bb.w);
                }
            }
        }

        __syncthreads();   // (B) all reads of sA[buf] done -> reuse as C stage
        uint8_t* sC = (uint8_t*)(smem + GM_SA_OFF + buf * GM_SA_BYTES);

        #pragma unroll
        for (int s = 0; s < 2; s++) {
            int r0 = mrow + s * 16 + qr;
            #pragma unroll
            for (int nt = 0; nt < 8; nt++) {
                int col = ncol + nt * 8 + qc * 2;
                *(uint16_t*)&sC[r0 * 128 + col] =
                    pk_e4m3x2(acc[s][nt][0], acc[s][nt][1]);
                *(uint16_t*)&sC[(r0 + 8) * 128 + col] =
                    pk_e4m3x2(acc[s][nt][2], acc[s][nt][3]);
            }
        }
        __syncthreads();   // (C) C tile complete

        #pragma unroll
        for (int k = 0; k < 4; k++) {
            int idx = tid + k * 256;
            int r = idx >> 3;
            int gr = row0 + r;
            if (gr < n) {
                uint4 v = *(const uint4*)&sC[idx * 16];
                *(uint4*)&tout[(size_t)gr * D + (idx & 7) * 16] = v;
            }
        }
        __syncthreads();   // (D) copy-out done before next prefetch reuses buffer
        buf ^= 1;
    }
}

// ================= aggregation: warp per node, fp8 gathers ========================
// Full 16-edge batches run UNPREDICATED (no bounds checks in the hot loop);
// a single predicated tail batch handles deg % 16.
__global__ void __launch_bounds__(256)
k_agg(const uint8_t* __restrict__ tin, const float* __restrict__ bias,
      __nv_bfloat16* __restrict__ hbout, int n, int last) {
    __shared__ float sCol[D];
    int tid = threadIdx.x;
    if (last) {
        if (tid < D) sCol[tid] = 0.0f;
        __syncthreads();
    }

    int wnode = (blockIdx.x * blockDim.x + tid) >> 5;   // warp = node
    int lane = tid & 31;
    int lane16 = lane & 15;
    int halfsel = (lane >> 4) * 8;                       // 0 or 8: edge window
    bool active = wnode < n;
    int s = 0, deg = 0;
    if (active) { s = g_row_off[wnode]; deg = g_row_off[wnode + 1] - s; }
    int coff = lane16 * 8;                               // fp8 col offset (8B)

    __half2 acc[4];
    #pragma unroll
    for (int j = 0; j < 4; j++) acc[j] = __half2(__float2half(0.f), __float2half(0.f));

    // ---- full batches: no predicates ----
    int base = s;
    int full_end = s + (deg & ~15);
    for (; base < full_end; base += 16) {
        int idx = g_csr[base + lane16];
        #pragma unroll
        for (int jb = 0; jb < 8; jb++) {
            int ij = __shfl_sync(0xffffffffu, idx, halfsel + jb);
            uint2 v = *(const uint2*)&tin[(size_t)ij * D + coff];
            uint16_t* p = (uint16_t*)&v;
            acc[0] = __hadd2(acc[0], e4m3x2_h2(p[0]));
            acc[1] = __hadd2(acc[1], e4m3x2_h2(p[1]));
            acc[2] = __hadd2(acc[2], e4m3x2_h2(p[2]));
            acc[3] = __hadd2(acc[3], e4m3x2_h2(p[3]));
        }
    }

    // ---- single predicated tail (deg % 16 edges) ----
    int m = s + deg - base;   // 0..15
    if (m > 0) {
        int idx = 0;
        if (lane16 < m) idx = g_csr[base + lane16];
        #pragma unroll
        for (int jb = 0; jb < 8; jb++) {
            int j = halfsel + jb;
            int ij = __shfl_sync(0xffffffffu, idx, j);
            if (j < m) {
                uint2 v = *(const uint2*)&tin[(size_t)ij * D + coff];
                uint16_t* p = (uint16_t*)&v;
                acc[0] = __hadd2(acc[0], e4m3x2_h2(p[0]));
                acc[1] = __hadd2(acc[1], e4m3x2_h2(p[1]));
                acc[2] = __hadd2(acc[2], e4m3x2_h2(p[2]));
                acc[3] = __hadd2(acc[3], e4m3x2_h2(p[3]));
            }
        }
    }

    // cross-half reduction (halves hold same cols, different edges)
    #pragma unroll
    for (int j = 0; j < 4; j++) {
        uint32_t u = *(uint32_t*)&acc[j];
        uint32_t o = __shfl_xor_sync(0xffffffffu, u, 16);
        acc[j] = __hadd2(acc[j], *(__half2*)&o);
    }

    if (active && lane < 16) {
        float a[8];
        #pragma unroll
        for (int j = 0; j < 4; j++) {
            float2 f = __half22float2(acc[j]);
            a[2 * j] = f.x; a[2 * j + 1] = f.y;
        }
        float inv = g_inv_in[wnode];
        float o[8];
        #pragma unroll
        for (int j = 0; j < 8; j++)
            o[j] = fmaxf(fmaf(a[j], inv, bias[coff + j]), 0.f);

        if (!last) {
            float so = g_inv_out[wnode];   // pre-scale for next gemm
            uint4 u;
            u.x = pk_bf16x2(o[0] * so, o[1] * so);
            u.y = pk_bf16x2(o[2] * so, o[3] * so);
            u.z = pk_bf16x2(o[4] * so, o[5] * so);
            u.w = pk_bf16x2(o[6] * so, o[7] * so);
            *(uint4*)&hbout[(size_t)wnode * D + coff] = u;
        } else {
            #pragma unroll
            for (int j = 0; j < 8; j++) atomicAdd(&sCol[coff + j], o[j]);
        }
    }

    if (last) {
        __syncthreads();
        if (tid < D) atomicAdd(&g_colsum[tid], sCol[tid]);
    }
}

// ================= epilogue =======================================================
__global__ void k_mlp(const float* __restrict__ Wl1, const float* __restrict__ bl1,
                      const float* __restrict__ Wl2, const float* __restrict__ bl2,
                      const float* __restrict__ Wo,  const float* __restrict__ bo,
                      float* __restrict__ out, int n) {
    __shared__ float s0[D], s1[D], s2[D];
    int t = threadIdx.x;
    s0[t] = g_colsum[t] * (1.0f / (float)n);
    __syncthreads();

    float a = bl1[t];
    for (int k = 0; k < D; k++) a = fmaf(s0[k], Wl1[k * D + t], a);
    s1[t] = fmaxf(a, 0.f);
    __syncthreads();

    float a2 = bl2[t];
    for (int k = 0; k < D; k++) a2 = fmaf(s1[k], Wl2[k * D + t], a2);
    s2[t] = fmaxf(a2, 0.f) * Wo[t];
    __syncthreads();

    for (int off = 64; off > 0; off >>= 1) {
        if (t < off) s2[t] += s2[t + off];
        __syncthreads();
    }
    if (t == 0) out[0] = s2[0] + bo[0];
}

// Tail cleanup: re-zero scratch for the NEXT graph replay.
__global__ void k_clean(int n) {
    int i = blockIdx.x * blockDim.x + threadIdx.x;
    if (i < n) { g_deg_out[i] = 0; g_deg_in[i] = 0; g_cursor[i] = 0; }
    if (i < D) g_colsum[i] = 0.0f;
    if (i < 256) g_bflag[i] = 0;
}

// ================= launch =========================================================
extern "C" void kernel_launch(void* const* d_in, const int* in_sizes, int n_in,
                              void* d_out, int out_size) {
    const float* x   = (const float*)d_in[0];
    const int*   src = (const int*)  d_in[1];
    const int*   dst = (const int*)  d_in[2];
    const float* W1  = (const float*)d_in[3];
    const float* b1  = (const float*)d_in[4];
    const float* W2  = (const float*)d_in[5];
    const float* b2  = (const float*)d_in[6];
    const float* W3  = (const float*)d_in[7];
    const float* b3  = (const float*)d_in[8];
    const float* W4  = (const float*)d_in[9];
    const float* b4  = (const float*)d_in[10];
    const float* Wl1 = (const float*)d_in[11];
    const float* bl1 = (const float*)d_in[12];
    const float* Wl2 = (const float*)d_in[13];
    const float* bl2 = (const float*)d_in[14];
    const float* Wo  = (const float*)d_in[15];
    const float* bo  = (const float*)d_in[16];
    float* out = (float*)d_out;

    int n = in_sizes[0] / D;
    int e = in_sizes[1];

    cudaFuncSetAttribute(k_gemm_mma, cudaFuncAttributeMaxDynamicSharedMemorySize,
                         GM_SMEM);

    __nv_bfloat16* hb;
    uint8_t* t;
    uint4* wf;
    cudaGetSymbolAddress((void**)&hb, g_hb);
    cudaGetSymbolAddress((void**)&t,  g_t);
    cudaGetSymbolAddress((void**)&wf, g_wfrag);

    int nb = (n + SCAN_B - 1) / SCAN_B;
    int ntiles = (n + 127) / 128;
    int ggrid  = ntiles < 296 ? ntiles : 296;
    int agg_grid = (n * 32 + 255) / 256;

    k_deg   <<<(e + 255) / 256, 256>>>(src, dst, e, W1, W2, W3, W4);  // 0
    k_scanf <<<nb, SCAN_B>>>(n);                                      // 1
    k_fillw <<<(e + 255) / 256, 256>>>(src, dst, e, x, n);            // 2

    // layer 1
    k_gemm_mma<<<ggrid, 256, GM_SMEM>>>(hb, wf + 0 * 2048, t, n, ntiles); // 3 <- ncu
    k_agg     <<<agg_grid, 256>>>(t, b1, hb, n, 0);
    // layer 2
    k_gemm_mma<<<ggrid, 256, GM_SMEM>>>(hb, wf + 1 * 2048, t, n, ntiles);
    k_agg     <<<agg_grid, 256>>>(t, b2, hb, n, 0);
    // layer 3
    k_gemm_mma<<<ggrid, 256, GM_SMEM>>>(hb, wf + 2 * 2048, t, n, ntiles);
    k_agg     <<<agg_grid, 256>>>(t, b3, hb, n, 0);
    // layer 4 (column-sum only)
    k_gemm_mma<<<ggrid, 256, GM_SMEM>>>(hb, wf + 3 * 2048, t, n, ntiles);
    k_agg     <<<agg_grid, 256>>>(t, b4, hb, n, 1);

    k_mlp  <<<1, D>>>(Wl1, bl1, Wl2, bl2, Wo, bo, out, n);
    k_clean<<<(n + 255) / 256, 256>>>(n);
}

// round 16
// speedup vs baseline: 1.2963x; 1.0926x over previous
#include <cuda_runtime.h>
#include <cuda_bf16.h>
#include <cuda_fp16.h>
#include <cstdint>

// Problem constants: N=100000 nodes, E=1.6M edges, D=128.
#define NMAX 100000
#define EMAX 1600000
#define D 128
#define SCAN_B 1024

// ================= scratch (static device globals; zero at module load) ===========
__device__ int   g_deg_out[NMAX];
__device__ int   g_deg_in [NMAX];
__device__ float g_inv_out[NMAX];
__device__ float g_inv_in [NMAX];
__device__ int   g_row_off[NMAX + 1];
__device__ int   g_cursor [NMAX];
__device__ int   g_csr    [EMAX];
__device__ int   g_bsum   [256];
__device__ int   g_bflag  [256];
__device__ __nv_bfloat16 g_hb[(size_t)NMAX * D];  // gemm input (pre-scaled by inv_out)
__device__ uint8_t g_t [(size_t)NMAX * D];        // e4m3 gather tensor (128B/row)
__device__ float g_colsum [D];
// W fragments per layer (bf16 m16n8k16): [kit(8)][nt2(8)][lane(32)] x uint4
__device__ uint4 g_wfrag  [4 * 2048];

__device__ __forceinline__ uint32_t pk_bf16x2(float lo, float hi) {
    __nv_bfloat162 t = __floats2bfloat162_rn(lo, hi);
    return *(uint32_t*)&t;
}

// two f32 -> packed e4m3x2 (low byte = lo)
__device__ __forceinline__ uint16_t pk_e4m3x2(float lo, float hi) {
    uint16_t r;
    asm("cvt.rn.satfinite.e4m3x2.f32 %0, %1, %2;" : "=h"(r) : "f"(hi), "f"(lo));
    return r;
}

// packed e4m3x2 -> f16x2 (low e4m3 -> low f16)
__device__ __forceinline__ __half2 e4m3x2_h2(uint16_t u) {
    uint32_t r;
    asm("cvt.rn.f16x2.e4m3x2 %0, %1;" : "=r"(r) : "h"(u));
    return *(__half2*)&r;
}

// m16n8k16 bf16 MMA, fp32 accumulate in place
__device__ __forceinline__ void mma_bf16(float* c, uint32_t a0, uint32_t a1,
                                         uint32_t a2, uint32_t a3,
                                         uint32_t b0, uint32_t b1) {
    asm volatile(
        "mma.sync.aligned.m16n8k16.row.col.f32.bf16.bf16.f32 "
        "{%0,%1,%2,%3}, {%4,%5,%6,%7}, {%8,%9}, {%0,%1,%2,%3};"
        : "+f"(c[0]), "+f"(c[1]), "+f"(c[2]), "+f"(c[3])
        : "r"(a0), "r"(a1), "r"(a2), "r"(a3), "r"(b0), "r"(b1));
}

// cp.async 16B global->shared; src_size=0 zero-fills (for out-of-range rows)
__device__ __forceinline__ void cp_async16(uint32_t saddr, const void* gptr, bool pred) {
    int sz = pred ? 16 : 0;
    asm volatile("cp.async.cg.shared.global [%0], [%1], 16, %2;"
                 :: "r"(saddr), "l"(gptr), "r"(sz));
}
#define CP_COMMIT() asm volatile("cp.async.commit_group;" ::: "memory")
#define CP_WAIT0()  asm volatile("cp.async.wait_group 0;" ::: "memory")
#define CP_WAIT1()  asm volatile("cp.async.wait_group 1;" ::: "memory")

// ================= k_deg: degree histogram + W fragment packing ===================
__global__ void k_deg(const int* __restrict__ src, const int* __restrict__ dst, int e,
                      const float* __restrict__ W1, const float* __restrict__ W2,
                      const float* __restrict__ W3, const float* __restrict__ W4) {
    int i = blockIdx.x * blockDim.x + threadIdx.x;
    if (i < e) {
        atomicAdd(&g_deg_out[src[i]], 1);
        atomicAdd(&g_deg_in [dst[i]], 1);
    }
    if (blockIdx.x < 4) {
        const float* W = (blockIdx.x == 0) ? W1 : (blockIdx.x == 1) ? W2
                       : (blockIdx.x == 2) ? W3 : W4;
        uint4* out = &g_wfrag[(size_t)blockIdx.x * 2048];
        for (int j = threadIdx.x; j < 2048; j += blockDim.x) {
            int lane = j & 31;
            int nt2  = (j >> 5) & 7;
            int kit  = j >> 8;             // 0..7
            int kk = kit * 16 + (lane & 3) * 2;
            int c0 = nt2 * 16 + (lane >> 2);
            uint4 v;
            v.x = pk_bf16x2(W[kk * D + c0],        W[(kk + 1) * D + c0]);
            v.y = pk_bf16x2(W[(kk + 8) * D + c0],  W[(kk + 9) * D + c0]);
            v.z = pk_bf16x2(W[kk * D + c0 + 8],    W[(kk + 1) * D + c0 + 8]);
            v.w = pk_bf16x2(W[(kk + 8) * D + c0 + 8], W[(kk + 9) * D + c0 + 8]);
            out[j] = v;
        }
    }
}

// ================= k_scanf: inv_sqrt + full prefix scan (decoupled aggregates) ====
__global__ void k_scanf(int n) {
    __shared__ int ssc[SCAN_B];
    __shared__ int swr[32];
    int t = threadIdx.x;
    int i = blockIdx.x * SCAN_B + t;

    if (i < n) {
        g_inv_out[i] = rsqrtf((float)max(g_deg_out[i], 1));
        g_inv_in [i] = rsqrtf((float)max(g_deg_in [i], 1));
    }

    int v = (i < n) ? g_deg_in[i] : 0;
    ssc[t] = v;
    __syncthreads();
    for (int off = 1; off < SCAN_B; off <<= 1) {
        int x2 = 0;
        if (t >= off) x2 = ssc[t - off];
        __syncthreads();
        ssc[t] += x2;
        __syncthreads();
    }

    if (t == SCAN_B - 1) {
        g_bsum[blockIdx.x] = ssc[t];
        __threadfence();
        atomicExch(&g_bflag[blockIdx.x], 1);
    }

    int part = 0;
    if (t < blockIdx.x) {
        while (((volatile int*)g_bflag)[t] == 0) {}
        part = ((volatile int*)g_bsum)[t];
    }
    #pragma unroll
    for (int off = 16; off > 0; off >>= 1)
        part += __shfl_down_sync(0xffffffffu, part, off);
    if ((t & 31) == 0) swr[t >> 5] = part;
    __syncthreads();
    if (t < 32) {
        int p = swr[t];
        #pragma unroll
        for (int off = 16; off > 0; off >>= 1)
            p += __shfl_down_sync(0xffffffffu, p, off);
        if (t == 0) swr[0] = p;
    }
    __syncthreads();
    int offset = swr[0];

    if (i < n) g_row_off[i + 1] = ssc[t] + offset;
    if (i == 0) g_row_off[0] = 0;
}

// ================= k_fillw: CSR fill + x prescale (x*inv_out -> bf16 g_hb) ========
__global__ void k_fillw(const int* __restrict__ src, const int* __restrict__ dst, int e,
                        const float* __restrict__ x, int n) {
    int gid = blockIdx.x * blockDim.x + threadIdx.x;
    int stride = gridDim.x * blockDim.x;

    if (gid < e) {
        int d = dst[gid];
        int p = g_row_off[d] + atomicAdd(&g_cursor[d], 1);
        g_csr[p] = src[gid];
    }

    const float4* x4 = (const float4*)x;
    uint2* hb2 = (uint2*)g_hb;
    int tot = n * (D / 4);
    for (int j = gid; j < tot; j += stride) {
        int r = j >> 5;
        float s = g_inv_out[r];
        float4 vv = x4[j];
        uint2 u;
        u.x = pk_bf16x2(vv.x * s, vv.y * s);
        u.y = pk_bf16x2(vv.z * s, vv.w * s);
        hb2[j] = u;
    }
}

// ================= tensor-core GEMM: t = hb @ W (hb pre-scaled), e4m3 out =========
#define GM_SW_U4 2048
#define GM_SA_OFF (GM_SW_U4 * 16)            // 32768 B
#define GM_SA_PAD 136                         // bf16 elements per row
#define GM_SA_BYTES (128 * GM_SA_PAD * 2)     // 34816 B per buffer
#define GM_SMEM (GM_SA_OFF + 2 * GM_SA_BYTES) // 102400 B

__global__ void __launch_bounds__(256, 2)
k_gemm_mma(const __nv_bfloat16* __restrict__ hin, const uint4* __restrict__ wfrag,
           uint8_t* __restrict__ tout, int n, int ntiles) {
    extern __shared__ char smem[];
    uint4* sW = (uint4*)smem;
    uint32_t sA_u32 = (uint32_t)__cvta_generic_to_shared(smem + GM_SA_OFF);

    int tid = threadIdx.x;
    int w = tid >> 5, lane = tid & 31;
    int qr = lane >> 2;        // 0..7
    int qc = lane & 3;         // 0..3
    int mrow = (w & 3) * 32;   // warp row base within tile
    int nc2_0 = (w >> 2) * 4;  // warp nt2 base (cols (w>>2)*64)
    int ncol = (w >> 2) * 64;

    for (int i = tid; i < GM_SW_U4; i += 256) sW[i] = wfrag[i];

    int st_r   = tid >> 4;
    int st_c16 = tid & 15;

    {
        int row0 = blockIdx.x * 128;
        #pragma unroll
        for (int k = 0; k < 8; k++) {
            int r = st_r + k * 16;
            int gr = row0 + r;
            cp_async16(sA_u32 + (uint32_t)(r * GM_SA_PAD + st_c16 * 8) * 2,
                       &hin[(size_t)gr * D + st_c16 * 8], gr < n);
        }
        CP_COMMIT();
    }

    int buf = 0;
    for (int tile = blockIdx.x; tile < ntiles; tile += gridDim.x) {
        int row0 = tile * 128;
        int ntile = tile + gridDim.x;

        if (ntile < ntiles) {
            int nrow0 = ntile * 128;
            uint32_t nb = sA_u32 + (buf ^ 1) * GM_SA_BYTES;
            #pragma unroll
            for (int k = 0; k < 8; k++) {
                int r = st_r + k * 16;
                int gr = nrow0 + r;
                cp_async16(nb + (uint32_t)(r * GM_SA_PAD + st_c16 * 8) * 2,
                           &hin[(size_t)gr * D + st_c16 * 8], gr < n);
            }
            CP_COMMIT();
            CP_WAIT1();
        } else {
            CP_WAIT0();
        }
        __syncthreads();   // (A) sA[buf] ready

        const __nv_bfloat16* sA =
            (const __nv_bfloat16*)(smem + GM_SA_OFF + buf * GM_SA_BYTES);

        float acc[2][8][4];
        #pragma unroll
        for (int s = 0; s < 2; s++)
            #pragma unroll
            for (int nt = 0; nt < 8; nt++)
                #pragma unroll
                for (int j = 0; j < 4; j++) acc[s][nt][j] = 0.0f;

        #pragma unroll
        for (int kitg = 0; kitg < 8; kitg++) {
            int kb = kitg * 16 + qc * 2;
            uint32_t a[2][4];
            #pragma unroll
            for (int s = 0; s < 2; s++) {
                int r0 = mrow + s * 16 + qr;
                a[s][0] = *(const uint32_t*)&sA[r0 * GM_SA_PAD + kb];
                a[s][1] = *(const uint32_t*)&sA[(r0 + 8) * GM_SA_PAD + kb];
                a[s][2] = *(const uint32_t*)&sA[r0 * GM_SA_PAD + kb + 8];
                a[s][3] = *(const uint32_t*)&sA[(r0 + 8) * GM_SA_PAD + kb + 8];
            }
            #pragma unroll
            for (int i = 0; i < 4; i++) {
                uint4 bb = sW[(kitg * 8 + nc2_0 + i) * 32 + lane];
                #pragma unroll
                for (int s = 0; s < 2; s++) {
                    mma_bf16(acc[s][2 * i],
                             a[s][0], a[s][1], a[s][2], a[s][3], bb.x, bb.y);
                    mma_bf16(acc[s][2 * i + 1],
                             a[s][0], a[s][1], a[s][2], a[s][3], bb.z, bb.w);
                }
            }
        }

        __syncthreads();   // (B) all reads of sA[buf] done -> reuse as C stage
        uint8_t* sC = (uint8_t*)(smem + GM_SA_OFF + buf * GM_SA_BYTES);

        #pragma unroll
        for (int s = 0; s < 2; s++) {
            int r0 = mrow + s * 16 + qr;
            #pragma unroll
            for (int nt = 0; nt < 8; nt++) {
                int col = ncol + nt * 8 + qc * 2;
                *(uint16_t*)&sC[r0 * 128 + col] =
                    pk_e4m3x2(acc[s][nt][0], acc[s][nt][1]);
                *(uint16_t*)&sC[(r0 + 8) * 128 + col] =
                    pk_e4m3x2(acc[s][nt][2], acc[s][nt][3]);
            }
        }
        __syncthreads();   // (C) C tile complete

        #pragma unroll
        for (int k = 0; k < 4; k++) {
            int idx = tid + k * 256;
            int r = idx >> 3;
            int gr = row0 + r;
            if (gr < n) {
                uint4 v = *(const uint4*)&sC[idx * 16];
                *(uint4*)&tout[(size_t)gr * D + (idx & 7) * 16] = v;
            }
        }
        __syncthreads();   // (D) copy-out done before next prefetch reuses buffer
        buf ^= 1;
    }
}

// ================= aggregation: warp per node, fp8 gathers, 8-edge batches ========
// Batch = 8 edges: half 0 (lanes 0-15) takes edges 0-3, half 1 takes 4-7.
// With deg~16 Poisson, ~84% of edges run in unpredicated full batches.
// 32-bit row offsets (N*D < 2^32) kill the IMAD.WIDE address chains.
__global__ void __launch_bounds__(256)
k_agg(const uint8_t* __restrict__ tin, const float* __restrict__ bias,
      __nv_bfloat16* __restrict__ hbout, int n, int last) {
    __shared__ float sCol[D];
    int tid = threadIdx.x;
    if (last) {
        if (tid < D) sCol[tid] = 0.0f;
        __syncthreads();
    }

    int wnode = (blockIdx.x * blockDim.x + tid) >> 5;   // warp = node
    int lane = tid & 31;
    int lane16 = lane & 15;
    int halfsel = (lane >> 4) * 4;                       // 0 or 4: edge window
    bool active = wnode < n;
    int s = 0, deg = 0;
    if (active) { s = g_row_off[wnode]; deg = g_row_off[wnode + 1] - s; }
    const uint8_t* tcol = tin + lane16 * 8;              // lane's column base

    __half2 acc[4];
    #pragma unroll
    for (int j = 0; j < 4; j++) acc[j] = __half2(__float2half(0.f), __float2half(0.f));

    // ---- full batches of 8: no predicates in the edge loop ----
    int base = s;
    int full_end = s + (deg & ~7);
    for (; base < full_end; base += 8) {
        int idx = 0;
        if (lane < 8) idx = g_csr[base + lane];          // one 32B load
        #pragma unroll
        for (int jb = 0; jb < 4; jb++) {
            int ij = __shfl_sync(0xffffffffu, idx, halfsel + jb);
            uint2 v = *(const uint2*)(tcol + ((uint32_t)ij << 7));
            uint16_t* p = (uint16_t*)&v;
            acc[0] = __hadd2(acc[0], e4m3x2_h2(p[0]));
            acc[1] = __hadd2(acc[1], e4m3x2_h2(p[1]));
            acc[2] = __hadd2(acc[2], e4m3x2_h2(p[2]));
            acc[3] = __hadd2(acc[3], e4m3x2_h2(p[3]));
        }
    }

    // ---- single predicated tail (deg % 8 edges) ----
    int m = s + deg - base;   // 0..7
    if (m > 0) {
        int idx = 0;
        if (lane < m) idx = g_csr[base + lane];
        #pragma unroll
        for (int jb = 0; jb < 4; jb++) {
            int j = halfsel + jb;
            int ij = __shfl_sync(0xffffffffu, idx, j);
            if (j < m) {
                uint2 v = *(const uint2*)(tcol + ((uint32_t)ij << 7));
                uint16_t* p = (uint16_t*)&v;
                acc[0] = __hadd2(acc[0], e4m3x2_h2(p[0]));
                acc[1] = __hadd2(acc[1], e4m3x2_h2(p[1]));
                acc[2] = __hadd2(acc[2], e4m3x2_h2(p[2]));
                acc[3] = __hadd2(acc[3], e4m3x2_h2(p[3]));
            }
        }
    }

    // cross-half reduction (halves hold same cols, different edges)
    #pragma unroll
    for (int j = 0; j < 4; j++) {
        uint32_t u = *(uint32_t*)&acc[j];
        uint32_t o = __shfl_xor_sync(0xffffffffu, u, 16);
        acc[j] = __hadd2(acc[j], *(__half2*)&o);
    }

    if (active && lane < 16) {
        int coff = lane16 * 8;
        float a[8];
        #pragma unroll
        for (int j = 0; j < 4; j++) {
            float2 f = __half22float2(acc[j]);
            a[2 * j] = f.x; a[2 * j + 1] = f.y;
        }
        float inv = g_inv_in[wnode];
        float4 bb0 = *(const float4*)&bias[coff];
        float4 bb1 = *(const float4*)&bias[coff + 4];
        float o[8];
        o[0] = fmaxf(fmaf(a[0], inv, bb0.x), 0.f);
        o[1] = fmaxf(fmaf(a[1], inv, bb0.y), 0.f);
        o[2] = fmaxf(fmaf(a[2], inv, bb0.z), 0.f);
        o[3] = fmaxf(fmaf(a[3], inv, bb0.w), 0.f);
        o[4] = fmaxf(fmaf(a[4], inv, bb1.x), 0.f);
        o[5] = fmaxf(fmaf(a[5], inv, bb1.y), 0.f);
        o[6] = fmaxf(fmaf(a[6], inv, bb1.z), 0.f);
        o[7] = fmaxf(fmaf(a[7], inv, bb1.w), 0.f);

        if (!last) {
            float so = g_inv_out[wnode];   // pre-scale for next gemm
            uint4 u;
            u.x = pk_bf16x2(o[0] * so, o[1] * so);
            u.y = pk_bf16x2(o[2] * so, o[3] * so);
            u.z = pk_bf16x2(o[4] * so, o[5] * so);
            u.w = pk_bf16x2(o[6] * so, o[7] * so);
            *(uint4*)&hbout[(size_t)wnode * D + coff] = u;
        } else {
            #pragma unroll
            for (int j = 0; j < 8; j++) atomicAdd(&sCol[coff + j], o[j]);
        }
    }

    if (last) {
        __syncthreads();
        if (tid < D) atomicAdd(&g_colsum[tid], sCol[tid]);
    }
}

// ================= epilogue =======================================================
__global__ void k_mlp(const float* __restrict__ Wl1, const float* __restrict__ bl1,
                      const float* __restrict__ Wl2, const float* __restrict__ bl2,
                      const float* __restrict__ Wo,  const float* __restrict__ bo,
                      float* __restrict__ out, int n) {
    __shared__ float s0[D], s1[D], s2[D];
    int t = threadIdx.x;
    s0[t] = g_colsum[t] * (1.0f / (float)n);
    __syncthreads();

    float a = bl1[t];
    for (int k = 0; k < D; k++) a = fmaf(s0[k], Wl1[k * D + t], a);
    s1[t] = fmaxf(a, 0.f);
    __syncthreads();

    float a2 = bl2[t];
    for (int k = 0; k < D; k++) a2 = fmaf(s1[k], Wl2[k * D + t], a2);
    s2[t] = fmaxf(a2, 0.f) * Wo[t];
    __syncthreads();

    for (int off = 64; off > 0; off >>= 1) {
        if (t < off) s2[t] += s2[t + off];
        __syncthreads();
    }
    if (t == 0) out[0] = s2[0] + bo[0];
}

// Tail cleanup: re-zero scratch for the NEXT graph replay.
__global__ void k_clean(int n) {
    int i = blockIdx.x * blockDim.x + threadIdx.x;
    if (i < n) { g_deg_out[i] = 0; g_deg_in[i] = 0; g_cursor[i] = 0; }
    if (i < D) g_colsum[i] = 0.0f;
    if (i < 256) g_bflag[i] = 0;
}

// ================= launch =========================================================
extern "C" void kernel_launch(void* const* d_in, const int* in_sizes, int n_in,
                              void* d_out, int out_size) {
    const float* x   = (const float*)d_in[0];
    const int*   src = (const int*)  d_in[1];
    const int*   dst = (const int*)  d_in[2];
    const float* W1  = (const float*)d_in[3];
    const float* b1  = (const float*)d_in[4];
    const float* W2  = (const float*)d_in[5];
    const float* b2  = (const float*)d_in[6];
    const float* W3  = (const float*)d_in[7];
    const float* b3  = (const float*)d_in[8];
    const float* W4  = (const float*)d_in[9];
    const float* b4  = (const float*)d_in[10];
    const float* Wl1 = (const float*)d_in[11];
    const float* bl1 = (const float*)d_in[12];
    const float* Wl2 = (const float*)d_in[13];
    const float* bl2 = (const float*)d_in[14];
    const float* Wo  = (const float*)d_in[15];
    const float* bo  = (const float*)d_in[16];
    float* out = (float*)d_out;

    int n = in_sizes[0] / D;
    int e = in_sizes[1];

    cudaFuncSetAttribute(k_gemm_mma, cudaFuncAttributeMaxDynamicSharedMemorySize,
                         GM_SMEM);

    __nv_bfloat16* hb;
    uint8_t* t;
    uint4* wf;
    cudaGetSymbolAddress((void**)&hb, g_hb);
    cudaGetSymbolAddress((void**)&t,  g_t);
    cudaGetSymbolAddress((void**)&wf, g_wfrag);

    int nb = (n + SCAN_B - 1) / SCAN_B;
    int ntiles = (n + 127) / 128;
    int ggrid  = ntiles < 296 ? ntiles : 296;
    int agg_grid = (n * 32 + 255) / 256;

    k_deg   <<<(e + 255) / 256, 256>>>(src, dst, e, W1, W2, W3, W4);  // 0
    k_scanf <<<nb, SCAN_B>>>(n);                                      // 1
    k_fillw <<<(e + 255) / 256, 256>>>(src, dst, e, x, n);            // 2

    // layer 1
    k_gemm_mma<<<ggrid, 256, GM_SMEM>>>(hb, wf + 0 * 2048, t, n, ntiles); // 3 <- ncu
    k_agg     <<<agg_grid, 256>>>(t, b1, hb, n, 0);
    // layer 2
    k_gemm_mma<<<ggrid, 256, GM_SMEM>>>(hb, wf + 1 * 2048, t, n, ntiles);
    k_agg     <<<agg_grid, 256>>>(t, b2, hb, n, 0);
    // layer 3
    k_gemm_mma<<<ggrid, 256, GM_SMEM>>>(hb, wf + 2 * 2048, t, n, ntiles);
    k_agg     <<<agg_grid, 256>>>(t, b3, hb, n, 0);
    // layer 4 (column-sum only)
    k_gemm_mma<<<ggrid, 256, GM_SMEM>>>(hb, wf + 3 * 2048, t, n, ntiles);
    k_agg     <<<agg_grid, 256>>>(t, b4, hb, n, 1);

    k_mlp  <<<1, D>>>(Wl1, bl1, Wl2, bl2, Wo, bo, out, n);
    k_clean<<<(n + 255) / 256, 256>>>(n);
}